// round 2
// baseline (speedup 1.0000x reference)
#include <cuda_runtime.h>
#include <cuda_bf16.h>

// LIF activation, forward:
//   decay[c] = 1 - w_leak[c]
//   gate  = (Vm < 1)  (strict)
//   Vm    = relu(x + decay*Vm*gate)
//   spike = (Vm > 1) ? 1 : 0  (strict)
// B=128, T=1000, C=512. Sequential in T per (b,c) lane; 16384 float4 lanes.
// R2: software-pipelined ping-pong load buffers -> loads always in flight.

namespace {
constexpr int B = 128;
constexpr int T = 1000;
constexpr int C = 512;
constexpr int C4 = C / 4;      // 128 float4 lanes per row
constexpr int U  = 8;          // block of timesteps per buffer
constexpr int NB = T / U;      // 125 blocks
constexpr int THREADS = 64;
}

// Load one block of U timesteps into a register buffer (streaming, no reuse).
#define LOADBLK(BUF, TBASE)                                              \
    do {                                                                 \
        _Pragma("unroll")                                                \
        for (int u = 0; u < U; u++)                                      \
            BUF[u] = __ldcs(xr + (size_t)((TBASE) + u) * C4);            \
    } while (0)

// Advance the recurrence over one block and store spikes (streaming).
#define COMPUTEBLK(BUF, TBASE)                                           \
    do {                                                                 \
        _Pragma("unroll")                                                \
        for (int u = 0; u < U; u++) {                                    \
            vx = fmaxf(0.0f, BUF[u].x + (vx < 1.0f ? dx * vx : 0.0f));   \
            vy = fmaxf(0.0f, BUF[u].y + (vy < 1.0f ? dy * vy : 0.0f));   \
            vz = fmaxf(0.0f, BUF[u].z + (vz < 1.0f ? dz * vz : 0.0f));   \
            vw = fmaxf(0.0f, BUF[u].w + (vw < 1.0f ? dw * vw : 0.0f));   \
            float4 s;                                                    \
            s.x = (vx > 1.0f) ? 1.0f : 0.0f;                             \
            s.y = (vy > 1.0f) ? 1.0f : 0.0f;                             \
            s.z = (vz > 1.0f) ? 1.0f : 0.0f;                             \
            s.w = (vw > 1.0f) ? 1.0f : 0.0f;                             \
            __stcs(orow + (size_t)((TBASE) + u) * C4, s);                \
        }                                                                \
    } while (0)

__global__ void __launch_bounds__(THREADS, 8)
lif_kernel(const float4* __restrict__ x4,
           const float4* __restrict__ wl4,
           float4* __restrict__ out4)
{
    const int tid = blockIdx.x * THREADS + threadIdx.x;  // one thread per (b, c4)
    const int c4  = tid & (C4 - 1);
    const int b   = tid >> 7;

    const float4 wl = wl4[c4];
    const float dx = 1.0f - wl.x;
    const float dy = 1.0f - wl.y;
    const float dz = 1.0f - wl.z;
    const float dw = 1.0f - wl.w;

    const size_t row0 = (size_t)b * (size_t)T * (size_t)C4 + (size_t)c4;
    const float4* __restrict__ xr   = x4  + row0;
    float4*       __restrict__ orow = out4 + row0;

    float vx = 0.0f, vy = 0.0f, vz = 0.0f, vw = 0.0f;

    float4 ba[U], bb[U];

    // Prologue: fill buffer A with block 0.
    LOADBLK(ba, 0);

    // Ping-pong: while computing one buffer, the other buffer's loads are in flight.
    for (int i = 0; i < NB; i += 2) {
        const int t1 = (i + 1) * U;
        if (i + 1 < NB) LOADBLK(bb, t1);     // prefetch block i+1
        COMPUTEBLK(ba, i * U);               // compute + store block i
        if (i + 1 < NB) {
            if (i + 2 < NB) LOADBLK(ba, (i + 2) * U);  // prefetch block i+2
            COMPUTEBLK(bb, t1);              // compute + store block i+1
        }
    }
}

extern "C" void kernel_launch(void* const* d_in, const int* in_sizes, int n_in,
                              void* d_out, int out_size)
{
    const float4* x4  = (const float4*)d_in[0];
    const float4* wl4 = (const float4*)d_in[1];
    float4* out4      = (float4*)d_out;

    const int total_threads = B * C4;             // 16384
    const int blocks = total_threads / THREADS;   // 256
    lif_kernel<<<blocks, THREADS>>>(x4, wl4, out4);
}

// round 3
// speedup vs baseline: 1.1107x; 1.1107x over previous
#include <cuda_runtime.h>
#include <cuda_bf16.h>

// LIF activation, forward:
//   decay[c] = 1 - w_leak[c]
//   gate  = (Vm < 1)  (strict)
//   Vm    = relu(x + decay*Vm*gate)
//   spike = (Vm > 1) ? 1 : 0  (strict)
// B=128, T=1000, C=512. Sequential in T per (b,c) lane.
// R3: scalar lanes -> 65536 threads / 2048 warps (4x R1) for latency hiding.

namespace {
constexpr int B = 128;
constexpr int T = 1000;
constexpr int C = 512;
constexpr int U = 10;          // timesteps batched per iteration (independent loads)
constexpr int THREADS = 128;
}

__global__ void __launch_bounds__(THREADS, 16)
lif_kernel(const float* __restrict__ x,
           const float* __restrict__ wl,
           float* __restrict__ out)
{
    const int tid = blockIdx.x * THREADS + threadIdx.x;  // one thread per (b, c)
    const int c   = tid & (C - 1);
    const int b   = tid >> 9;                             // tid / C

    const float d = 1.0f - wl[c];                         // decay

    const size_t row0 = (size_t)b * (size_t)T * (size_t)C + (size_t)c;
    const float* __restrict__ xr   = x   + row0;
    float*       __restrict__ orow = out + row0;

    float v = 0.0f;

    #pragma unroll 1
    for (int t0 = 0; t0 < T; t0 += U) {
        // Batch U independent stride-C loads (coalesced 128B wavefronts per warp).
        float xv[U];
        #pragma unroll
        for (int u = 0; u < U; u++)
            xv[u] = __ldcs(xr + (size_t)(t0 + u) * C);

        #pragma unroll
        for (int u = 0; u < U; u++) {
            // hard reset: keep decayed membrane only if strictly below threshold
            v = fmaxf(0.0f, xv[u] + (v < 1.0f ? d * v : 0.0f));
            // flat-surrogate spike: strictly above threshold
            __stcs(orow + (size_t)(t0 + u) * C, (v > 1.0f) ? 1.0f : 0.0f);
        }
    }
}

extern "C" void kernel_launch(void* const* d_in, const int* in_sizes, int n_in,
                              void* d_out, int out_size)
{
    const float* x   = (const float*)d_in[0];   // x [B,T,C]
    const float* wl  = (const float*)d_in[1];   // w_leak [C]
    float* out       = (float*)d_out;           // [B,T,C] f32

    const int total_threads = B * C;              // 65536
    const int blocks = total_threads / THREADS;   // 512
    lif_kernel<<<blocks, THREADS>>>(x, wl, out);
}

// round 4
// speedup vs baseline: 1.3998x; 1.2603x over previous
#include <cuda_runtime.h>
#include <cuda_bf16.h>
#include <cstdint>

// LIF activation, forward:
//   decay[c] = 1 - w_leak[c]
//   gate  = (Vm < 1)  (strict)
//   Vm    = relu(x + decay*Vm*gate)
//   spike = (Vm > 1) ? 1 : 0  (strict)
// B=128, T=1000, C=512.
// R4: bulk-async (TMA) streaming through SMEM to bypass the per-SM LDG
// outstanding-request cap that pinned R1-R3 at ~4.3 TB/s.
//   - 128 CTAs, one per batch b; slab x[b] = 2MB contiguous.
//   - IN ring: 5 stages x 20KB (10 timesteps), mbarrier complete_tx.
//   - OUT ring: 2 stages x 20KB, bulk_group stores.

namespace {
constexpr int B = 128;
constexpr int T = 1000;
constexpr int C = 512;
constexpr int CHUNK_T   = 10;                       // timesteps per chunk
constexpr int NCHUNKS   = T / CHUNK_T;              // 100
constexpr uint32_t CH_BYTES  = CHUNK_T * C * 4;     // 20480
constexpr int IN_STAGES  = 5;
constexpr int OUT_STAGES = 2;
constexpr int THREADS = 512;

constexpr uint32_t SMEM_IN   = 0;
constexpr uint32_t SMEM_OUT  = IN_STAGES * CH_BYTES;                 // 102400
constexpr uint32_t SMEM_MBAR = SMEM_OUT + OUT_STAGES * CH_BYTES;     // 143360
constexpr uint32_t SMEM_TOTAL = SMEM_MBAR + IN_STAGES * 8 + 64;      // + barriers
}

__device__ __forceinline__ uint32_t smem_u32(const void* p) {
    uint32_t a;
    asm("{ .reg .u64 t; cvta.to.shared.u64 t, %1; cvt.u32.u64 %0, t; }" : "=r"(a) : "l"(p));
    return a;
}

__device__ __forceinline__ void mbar_init(uint32_t mbar, uint32_t cnt) {
    asm volatile("mbarrier.init.shared.b64 [%0], %1;" :: "r"(mbar), "r"(cnt) : "memory");
}
__device__ __forceinline__ void mbar_expect_tx(uint32_t mbar, uint32_t bytes) {
    asm volatile("mbarrier.arrive.expect_tx.shared.b64 _, [%0], %1;" :: "r"(mbar), "r"(bytes) : "memory");
}
__device__ __forceinline__ void mbar_wait(uint32_t mbar, uint32_t parity) {
    uint32_t done;
    asm volatile(
        "{\n\t.reg .pred p;\n\t"
        "mbarrier.try_wait.parity.acquire.cta.shared::cta.b64 p, [%1], %2;\n\t"
        "selp.b32 %0, 1, 0, p;\n\t}"
        : "=r"(done) : "r"(mbar), "r"(parity) : "memory");
    while (!done) {
        asm volatile(
            "{\n\t.reg .pred p;\n\t"
            "mbarrier.try_wait.parity.acquire.cta.shared::cta.b64 p, [%1], %2, 0x989680;\n\t"
            "selp.b32 %0, 1, 0, p;\n\t}"
            : "=r"(done) : "r"(mbar), "r"(parity) : "memory");
    }
}
__device__ __forceinline__ void bulk_load(uint32_t smem_dst, const void* gmem_src,
                                          uint32_t bytes, uint32_t mbar) {
    asm volatile(
        "cp.async.bulk.shared::cta.global.mbarrier::complete_tx::bytes [%0], [%1], %2, [%3];"
        :: "r"(smem_dst), "l"(gmem_src), "r"(bytes), "r"(mbar) : "memory");
}
__device__ __forceinline__ void bulk_store(void* gmem_dst, uint32_t smem_src, uint32_t bytes) {
    asm volatile(
        "cp.async.bulk.global.shared::cta.bulk_group [%0], [%1], %2;"
        :: "l"(gmem_dst), "r"(smem_src), "r"(bytes) : "memory");
}

__global__ void __launch_bounds__(THREADS, 1)
lif_kernel(const float* __restrict__ x,
           const float* __restrict__ wl,
           float* __restrict__ out)
{
    extern __shared__ __align__(1024) char smem[];
    const uint32_t sbase = smem_u32(smem);
    const int tid = threadIdx.x;
    const int b   = blockIdx.x;
    const int c   = tid;                       // one thread per channel

    const float d = 1.0f - wl[c];
    float v = 0.0f;

    const float* __restrict__ xslab = x   + (size_t)b * T * C;   // 2MB contiguous
    float*       __restrict__ oslab = out + (size_t)b * T * C;

    // Init mbarriers (count=1: expect_tx performs the single arrive)
    if (tid == 0) {
        #pragma unroll
        for (int s = 0; s < IN_STAGES; s++)
            mbar_init(sbase + SMEM_MBAR + s * 8, 1);
    }
    __syncthreads();

    // Prologue: fill all IN stages (chunks 0..4)
    if (tid == 0) {
        #pragma unroll
        for (int s = 0; s < IN_STAGES; s++) {
            const uint32_t mbar = sbase + SMEM_MBAR + s * 8;
            mbar_expect_tx(mbar, CH_BYTES);
            bulk_load(sbase + SMEM_IN + s * CH_BYTES,
                      xslab + (size_t)s * CHUNK_T * C, CH_BYTES, mbar);
        }
    }

    for (int i = 0; i < NCHUNKS; i++) {
        const int s   = i % IN_STAGES;
        const int o   = i % OUT_STAGES;
        const uint32_t parity = (uint32_t)((i / IN_STAGES) & 1);
        const uint32_t mbar   = sbase + SMEM_MBAR + s * 8;

        // Wait for input chunk i
        mbar_wait(mbar, parity);

        // Ensure the out-buffer's previous bulk store (chunk i-2) has read smem
        if (tid == 0)
            asm volatile("cp.async.bulk.wait_group.read 1;" ::: "memory");
        __syncthreads();

        const float* sin  = (const float*)(smem + SMEM_IN  + s * CH_BYTES);
        float*       sout = (float*)      (smem + SMEM_OUT + o * CH_BYTES);

        // Batch the 10 independent LDS, then run the serial recurrence
        float xv[CHUNK_T];
        #pragma unroll
        for (int u = 0; u < CHUNK_T; u++)
            xv[u] = sin[u * C + c];

        #pragma unroll
        for (int u = 0; u < CHUNK_T; u++) {
            v = fmaxf(0.0f, xv[u] + (v < 1.0f ? d * v : 0.0f));
            sout[u * C + c] = (v > 1.0f) ? 1.0f : 0.0f;
        }

        __syncthreads();   // all spikes for chunk i written to smem

        if (tid == 0) {
            // generic-proxy smem writes -> visible to async proxy
            asm volatile("fence.proxy.async.shared::cta;" ::: "memory");
            bulk_store(oslab + (size_t)i * CHUNK_T * C,
                       sbase + SMEM_OUT + o * CH_BYTES, CH_BYTES);
            asm volatile("cp.async.bulk.commit_group;" ::: "memory");

            // Refill this IN stage with chunk i+5 (consumers are past the wait)
            const int nxt = i + IN_STAGES;
            if (nxt < NCHUNKS) {
                mbar_expect_tx(mbar, CH_BYTES);
                bulk_load(sbase + SMEM_IN + s * CH_BYTES,
                          xslab + (size_t)nxt * CHUNK_T * C, CH_BYTES, mbar);
            }
        }
    }

    // Drain all pending bulk stores before exit
    if (tid == 0)
        asm volatile("cp.async.bulk.wait_group 0;" ::: "memory");
}

extern "C" void kernel_launch(void* const* d_in, const int* in_sizes, int n_in,
                              void* d_out, int out_size)
{
    const float* x  = (const float*)d_in[0];   // x [B,T,C]
    const float* wl = (const float*)d_in[1];   // w_leak [C]
    float* out      = (float*)d_out;

    cudaFuncSetAttribute(lif_kernel, cudaFuncAttributeMaxDynamicSharedMemorySize,
                         (int)SMEM_TOTAL);
    lif_kernel<<<B, THREADS, SMEM_TOTAL>>>(x, wl, out);
}

// round 5
// speedup vs baseline: 1.4097x; 1.0071x over previous
#include <cuda_runtime.h>
#include <cuda.h>
#include <cuda_bf16.h>
#include <cstdint>

// LIF activation, forward:
//   decay[c] = 1 - w_leak[c]
//   gate  = (Vm < 1)  (strict)
//   Vm    = relu(x + decay*Vm*gate)
//   spike = (Vm > 1) ? 1 : 0  (strict)
// B=128, T=1000, C=512.
// R5: split C in half -> 256 CTAs (2/SM, all 148 SMs active), 2D-TMA tensor-map
// loads/stores (box 256 x CHUNK_T) through a 7-stage smem ring.

namespace {
constexpr int B = 128;
constexpr int T = 1000;
constexpr int C = 512;
constexpr int CH = 256;                            // channels per CTA
constexpr int CHUNK_T = 10;                        // timesteps per chunk
constexpr int NCHUNKS = T / CHUNK_T;               // 100
constexpr uint32_t CH_BYTES = CHUNK_T * CH * 4;    // 10240
constexpr int IN_STAGES  = 7;
constexpr int OUT_STAGES = 2;
constexpr int THREADS = CH;                        // 256, one per channel

constexpr uint32_t SMEM_IN   = 0;
constexpr uint32_t SMEM_OUT  = IN_STAGES * CH_BYTES;               // 71680
constexpr uint32_t SMEM_MBAR = SMEM_OUT + OUT_STAGES * CH_BYTES;   // 92160
constexpr uint32_t SMEM_TOTAL = SMEM_MBAR + IN_STAGES * 8 + 64;
}

__device__ __forceinline__ uint32_t smem_u32(const void* p) {
    uint32_t a;
    asm("{ .reg .u64 t; cvta.to.shared.u64 t, %1; cvt.u32.u64 %0, t; }" : "=r"(a) : "l"(p));
    return a;
}
__device__ __forceinline__ void mbar_init(uint32_t mbar, uint32_t cnt) {
    asm volatile("mbarrier.init.shared.b64 [%0], %1;" :: "r"(mbar), "r"(cnt) : "memory");
}
__device__ __forceinline__ void mbar_expect_tx(uint32_t mbar, uint32_t bytes) {
    asm volatile("mbarrier.arrive.expect_tx.shared.b64 _, [%0], %1;" :: "r"(mbar), "r"(bytes) : "memory");
}
__device__ __forceinline__ void mbar_wait(uint32_t mbar, uint32_t parity) {
    uint32_t done;
    asm volatile(
        "{\n\t.reg .pred p;\n\t"
        "mbarrier.try_wait.parity.acquire.cta.shared::cta.b64 p, [%1], %2;\n\t"
        "selp.b32 %0, 1, 0, p;\n\t}"
        : "=r"(done) : "r"(mbar), "r"(parity) : "memory");
    while (!done) {
        asm volatile(
            "{\n\t.reg .pred p;\n\t"
            "mbarrier.try_wait.parity.acquire.cta.shared::cta.b64 p, [%1], %2, 0x989680;\n\t"
            "selp.b32 %0, 1, 0, p;\n\t}"
            : "=r"(done) : "r"(mbar), "r"(parity) : "memory");
    }
}
__device__ __forceinline__ void tma_load2d(uint32_t smem_dst, const CUtensorMap* map,
                                           int cx, int cy, uint32_t mbar) {
    asm volatile(
        "cp.async.bulk.tensor.2d.shared::cta.global.tile.mbarrier::complete_tx::bytes "
        "[%0], [%1, {%2, %3}], [%4];"
        :: "r"(smem_dst), "l"(map), "r"(cx), "r"(cy), "r"(mbar) : "memory");
}
__device__ __forceinline__ void tma_store2d(const CUtensorMap* map, int cx, int cy,
                                            uint32_t smem_src) {
    asm volatile(
        "cp.async.bulk.tensor.2d.global.shared::cta.tile.bulk_group [%0, {%1, %2}], [%3];"
        :: "l"(map), "r"(cx), "r"(cy), "r"(smem_src) : "memory");
}

__global__ void __launch_bounds__(THREADS, 2)
lif_kernel(const __grid_constant__ CUtensorMap in_map,
           const __grid_constant__ CUtensorMap out_map,
           const float* __restrict__ wl)
{
    extern __shared__ __align__(1024) char smem[];
    const uint32_t sbase = smem_u32(smem);
    const int tid = threadIdx.x;
    const int b   = blockIdx.x >> 1;
    const int c0  = (blockIdx.x & 1) << 8;     // 0 or 256
    const int c   = tid;

    const float d = 1.0f - wl[c0 + c];
    float v = 0.0f;

    const int ybase = b * T;                   // row in the [B*T, C] view

    if (tid == 0) {
        #pragma unroll
        for (int s = 0; s < IN_STAGES; s++)
            mbar_init(sbase + SMEM_MBAR + s * 8, 1);
    }
    __syncthreads();

    // Prologue: fill the IN ring
    if (tid == 0) {
        #pragma unroll
        for (int s = 0; s < IN_STAGES; s++) {
            const uint32_t mbar = sbase + SMEM_MBAR + s * 8;
            mbar_expect_tx(mbar, CH_BYTES);
            tma_load2d(sbase + SMEM_IN + s * CH_BYTES, &in_map,
                       c0, ybase + s * CHUNK_T, mbar);
        }
    }

    int s = 0, parity = 0;
    for (int i = 0; i < NCHUNKS; i++) {
        const int o = i & (OUT_STAGES - 1);
        const uint32_t mbar = sbase + SMEM_MBAR + s * 8;

        mbar_wait(mbar, (uint32_t)parity);

        // OUT ring reuse: store of chunk i-2 must have finished reading smem
        if (tid == 0)
            asm volatile("cp.async.bulk.wait_group.read 1;" ::: "memory");
        __syncthreads();

        const float* sin  = (const float*)(smem + SMEM_IN  + s * CH_BYTES);
        float*       sout = (float*)      (smem + SMEM_OUT + o * CH_BYTES);

        float xv[CHUNK_T];
        #pragma unroll
        for (int u = 0; u < CHUNK_T; u++)
            xv[u] = sin[u * CH + c];

        #pragma unroll
        for (int u = 0; u < CHUNK_T; u++) {
            v = fmaxf(0.0f, xv[u] + (v < 1.0f ? d * v : 0.0f));
            sout[u * CH + c] = (v > 1.0f) ? 1.0f : 0.0f;
        }

        __syncthreads();   // spikes for chunk i in smem

        if (tid == 0) {
            asm volatile("fence.proxy.async.shared::cta;" ::: "memory");
            tma_store2d(&out_map, c0, ybase + i * CHUNK_T,
                        sbase + SMEM_OUT + o * CH_BYTES);
            asm volatile("cp.async.bulk.commit_group;" ::: "memory");

            const int nxt = i + IN_STAGES;
            if (nxt < NCHUNKS) {
                mbar_expect_tx(mbar, CH_BYTES);
                tma_load2d(sbase + SMEM_IN + s * CH_BYTES, &in_map,
                           c0, ybase + nxt * CHUNK_T, mbar);
            }
        }

        if (++s == IN_STAGES) { s = 0; parity ^= 1; }
    }

    if (tid == 0)
        asm volatile("cp.async.bulk.wait_group 0;" ::: "memory");
}

// ---------------- host ----------------

typedef CUresult (*PFN_encodeTiled)(
    CUtensorMap*, CUtensorMapDataType, cuuint32_t, void*,
    const cuuint64_t*, const cuuint64_t*, const cuuint32_t*, const cuuint32_t*,
    CUtensorMapInterleave, CUtensorMapSwizzle, CUtensorMapL2promotion,
    CUtensorMapFloatOOBfill);

static void make_map(PFN_encodeTiled enc, CUtensorMap* m, void* base) {
    cuuint64_t dims[2]    = {(cuuint64_t)C, (cuuint64_t)B * (cuuint64_t)T};
    cuuint64_t strides[1] = {(cuuint64_t)C * 4};
    cuuint32_t box[2]     = {(cuuint32_t)CH, (cuuint32_t)CHUNK_T};
    cuuint32_t estr[2]    = {1, 1};
    enc(m, CU_TENSOR_MAP_DATA_TYPE_FLOAT32, 2, base, dims, strides, box, estr,
        CU_TENSOR_MAP_INTERLEAVE_NONE, CU_TENSOR_MAP_SWIZZLE_NONE,
        CU_TENSOR_MAP_L2_PROMOTION_L2_128B, CU_TENSOR_MAP_FLOAT_OOB_FILL_NONE);
}

extern "C" void kernel_launch(void* const* d_in, const int* in_sizes, int n_in,
                              void* d_out, int out_size)
{
    void* x   = (void*)d_in[0];                 // x [B,T,C] f32
    const float* wl = (const float*)d_in[1];    // w_leak [C]

    // Driver entry point without a -lcuda link dependency.
    PFN_encodeTiled enc = nullptr;
    {
        void* p = nullptr;
        cudaDriverEntryPointQueryResult qr;
        cudaGetDriverEntryPointByVersion("cuTensorMapEncodeTiled", &p, 12000,
                                         cudaEnableDefault, &qr);
        enc = (PFN_encodeTiled)p;
    }

    CUtensorMap in_map, out_map;
    make_map(enc, &in_map, x);
    make_map(enc, &out_map, d_out);

    cudaFuncSetAttribute(lif_kernel, cudaFuncAttributeMaxDynamicSharedMemorySize,
                         (int)SMEM_TOTAL);
    lif_kernel<<<B * 2, THREADS, SMEM_TOTAL>>>(in_map, out_map, wl);
}